// round 2
// baseline (speedup 1.0000x reference)
#include <cuda_runtime.h>

#define NQ    12
#define DEPTH 6
#define TPB   128

typedef unsigned int u32;
typedef unsigned long long u64;

// ---------------------------------------------------------------------------
// Wire q <-> flat-index bit (11-q). CNOT ring tracked as GF(2)-linear storage
// permutation; Q_d = F^d columns precomputed (with smem swizzle composed in).
// ---------------------------------------------------------------------------
__host__ __device__ constexpr u32 Fmap(u32 b) {
    for (int g = 11; g >= 0; --g) {
        int c = 11 - g, t = (c + 11) % NQ;
        b ^= ((b >> c) & 1u) << t;
    }
    return b;
}
__host__ __device__ constexpr u32 Finvmap(u32 b) {
    for (int g = 0; g < NQ; ++g) {
        int c = 11 - g, t = (c + 11) % NQ;
        b ^= ((b >> c) & 1u) << t;
    }
    return b;
}
__host__ __device__ constexpr u32 swz(u32 x) { return x ^ ((x >> 5) & 31u); }

struct Tabs {
    u32 q[DEPTH][NQ];  // swizzled columns of Q_d = F^d
    u32 finv[NQ];      // columns of F^{-1} (logical space, for final weights)
};
__host__ __device__ constexpr Tabs mk_tabs() {
    Tabs t{};
    u32 raw[NQ] = {};
    for (int j = 0; j < NQ; ++j) { raw[j] = 1u << j; t.q[0][j] = swz(raw[j]); }
    for (int d = 1; d < DEPTH; ++d)
        for (int j = 0; j < NQ; ++j) { raw[j] = Fmap(raw[j]); t.q[d][j] = swz(raw[j]); }
    for (int j = 0; j < NQ; ++j) t.finv[j] = Finvmap(1u << j);
    return t;
}
__constant__ Tabs TAB = mk_tabs();

// Pass p owns 5 bit-directions; gates on the first 4; the 5th (DIRS[p][4]) is
// the f32x2 SIMD lane. Filler bits come from threadIdx in FILL[p] order.
__constant__ int DIRS[3][5] = {{0,1,2,3,4},{4,5,6,7,8},{8,9,10,11,0}};
__constant__ int FILL[3][7] = {{5,6,7,8,9,10,11},{0,1,2,3,9,10,11},{1,2,3,4,5,6,7}};

// ---- packed f32x2 helpers (FFMA2 only reachable via PTX) -------------------
__device__ __forceinline__ u64 pk(float lo, float hi) {
    u64 r; asm("mov.b64 %0, {%1, %2};" : "=l"(r) : "f"(lo), "f"(hi)); return r;
}
__device__ __forceinline__ void upk(float& lo, float& hi, u64 v) {
    asm("mov.b64 {%0, %1}, %2;" : "=f"(lo), "=f"(hi) : "l"(v));
}
__device__ __forceinline__ u64 fma2(u64 a, u64 b, u64 c) {
    u64 d; asm("fma.rn.f32x2 %0, %1, %2, %3;" : "=l"(d) : "l"(a), "l"(b), "l"(c)); return d;
}
__device__ __forceinline__ u64 mul2(u64 a, u64 b) {
    u64 d; asm("mul.rn.f32x2 %0, %1, %2;" : "=l"(d) : "l"(a), "l"(b)); return d;
}

__global__ void __launch_bounds__(TPB, 4)
qsim_kernel(const float* __restrict__ inp, const float* __restrict__ wp,
            float* __restrict__ out)
{
    __shared__ float2 sv[1 << NQ];                 // 32 KB state (AoS re,im)
    __shared__ u64    gdt[DEPTH * NQ * 12];        // 6.75 KB duplicated gate consts
    __shared__ float  csm[NQ * 2];                 // encode cos/sin per bit
    __shared__ float  red[TPB / 32];

    const int t   = threadIdx.x;
    const int bid = blockIdx.x;

    // ---- per-block prep: duplicated packed gate constants + encode factors --
    if (t < DEPTH * NQ) {
        int d = t / NQ, m = t % NQ;               // m = bit index, wire = 11-m
        int wo = (d * NQ + (11 - m)) * 3;
        float phi = wp[wo + 0], th = wp[wo + 1], om = wp[wo + 2];
        float st, ct; sincosf(0.5f * th, &st, &ct);
        float sa, ca; sincosf(0.5f * (phi + om), &sa, &ca);
        float sb, cb; sincosf(0.5f * (phi - om), &sb, &cb);
        // Rot = [[(A,B)=(ct*ca,-ct*sa), (C,D)=(-st*cb,-st*sb)],
        //        [(E,F)=( st*cb,-st*sb), (G,H)=( ct*ca, ct*sa)]]
        float A =  ct * ca, B = -ct * sa;
        float C = -st * cb, D = -st * sb;
        float E =  st * cb, F = -st * sb;
        float G =  ct * ca, H =  ct * sa;
        u64* gp = &gdt[t * 12];
        gp[0]  = pk(A,  A);  gp[1]  = pk(B,  B);  gp[2]  = pk(-B, -B);
        gp[3]  = pk(C,  C);  gp[4]  = pk(D,  D);  gp[5]  = pk(-D, -D);
        gp[6]  = pk(E,  E);  gp[7]  = pk(F,  F);  gp[8]  = pk(-F, -F);
        gp[9]  = pk(G,  G);  gp[10] = pk(H,  H);  gp[11] = pk(-H, -H);
    }
    if (t < NQ) {
        float x = inp[bid * NQ + (11 - t)];       // bit t <- wire 11-t
        float s, c; sincosf(0.5f * x, &s, &c);
        csm[t * 2 + 0] = c; csm[t * 2 + 1] = s;
    }
    __syncthreads();

    u64 acc2 = 0ull;

    for (int d = 0; d < DEPTH; ++d) {
        const u32* qc = TAB.q[d];
        for (int p = 0; p < 3; ++p) {
            u32 pb = 0;
            #pragma unroll
            for (int j = 0; j < 7; ++j)
                if ((t >> j) & 1) pb ^= qc[FILL[p][j]];
            u32 qd[5];
            #pragma unroll
            for (int k = 0; k < 5; ++k) qd[k] = qc[DIRS[p][k]];

            // State: slot index k (4 gate bits) x SIMD lane (5th owned bit).
            u64 R[16], I[16];
            if (d == 0 && p == 0) {
                // ---- angle encoding: psi[b] = prod_m (b_m ? sin : cos) ----
                float f = csm[5 * 2 + (t & 1)];
                #pragma unroll
                for (int j = 1; j < 7; ++j) f *= csm[(5 + j) * 2 + ((t >> j) & 1)];
                float v[32]; v[0] = f;
                #pragma unroll
                for (int j = 0; j < 5; ++j) {
                    #pragma unroll
                    for (int k = 0; k < (1 << j); ++k) {
                        float lo = v[k];
                        v[k]            = lo * csm[j * 2 + 0];
                        v[k + (1 << j)] = lo * csm[j * 2 + 1];
                    }
                }
                #pragma unroll
                for (int k = 0; k < 16; ++k) {
                    R[k] = pk(v[k], v[k | 16]);
                    I[k] = 0ull;
                }
            } else {
                #pragma unroll
                for (int k = 0; k < 16; ++k) {
                    u32 a = pb;
                    if (k & 1) a ^= qd[0];
                    if (k & 2) a ^= qd[1];
                    if (k & 4) a ^= qd[2];
                    if (k & 8) a ^= qd[3];
                    float2 va = sv[a], vb = sv[a ^ qd[4]];
                    R[k] = pk(va.x, vb.x);
                    I[k] = pk(va.y, vb.y);
                }
            }

            // ---- 4 register-resident gates, lane-wise packed complex math --
            const u64* gp = &gdt[(d * NQ + p * 4) * 12];
            #pragma unroll
            for (int g = 0; g < 4; ++g) {
                u64 A  = gp[12*g+0], B  = gp[12*g+1], Bn = gp[12*g+2];
                u64 C  = gp[12*g+3], D  = gp[12*g+4], Dn = gp[12*g+5];
                u64 E  = gp[12*g+6], F  = gp[12*g+7], Fn = gp[12*g+8];
                u64 G  = gp[12*g+9], H  = gp[12*g+10], Hn = gp[12*g+11];
                #pragma unroll
                for (int k = 0; k < 16; ++k) {
                    if (!((k >> g) & 1)) {
                        int k1 = k | (1 << g);
                        u64 R0 = R[k], I0 = I[k], R1 = R[k1], I1 = I[k1];
                        u64 nR0 = fma2(A, R0, fma2(Bn, I0, fma2(C, R1, mul2(Dn, I1))));
                        u64 nI0 = fma2(A, I0, fma2(B,  R0, fma2(C, I1, mul2(D,  R1))));
                        u64 nR1 = fma2(E, R0, fma2(Fn, I0, fma2(G, R1, mul2(Hn, I1))));
                        u64 nI1 = fma2(E, I0, fma2(F,  R0, fma2(G, I1, mul2(H,  R1))));
                        R[k] = nR0; I[k] = nI0; R[k1] = nR1; I[k1] = nI1;
                    }
                }
            }

            if (d == DEPTH - 1 && p == 2) {
                // ---- fold final ring + <Z> mean into packed reduction ------
                u32 fb = 0;
                #pragma unroll
                for (int j = 0; j < 7; ++j)
                    if ((t >> j) & 1) fb ^= TAB.finv[FILL[2][j]];
                u32 fd[5];
                #pragma unroll
                for (int k = 0; k < 5; ++k) fd[k] = TAB.finv[DIRS[2][k]];
                #pragma unroll
                for (int k = 0; k < 16; ++k) {
                    u32 fv = fb;
                    if (k & 1) fv ^= fd[0];
                    if (k & 2) fv ^= fd[1];
                    if (k & 4) fv ^= fd[2];
                    if (k & 8) fv ^= fd[3];
                    float w0 = (float)(NQ - 2 * __popc(fv));
                    float w1 = (float)(NQ - 2 * __popc(fv ^ fd[4]));
                    u64 P = fma2(I[k], I[k], mul2(R[k], R[k]));
                    acc2 = fma2(P, pk(w0, w1), acc2);
                }
            } else {
                #pragma unroll
                for (int k = 0; k < 16; ++k) {
                    u32 a = pb;
                    if (k & 1) a ^= qd[0];
                    if (k & 2) a ^= qd[1];
                    if (k & 4) a ^= qd[2];
                    if (k & 8) a ^= qd[3];
                    float2 va, vb;
                    upk(va.x, vb.x, R[k]);
                    upk(va.y, vb.y, I[k]);
                    sv[a] = va; sv[a ^ qd[4]] = vb;
                }
                __syncthreads();
            }
        }
    }

    // ---- block reduction -> out[bid] ----
    float alo, ahi; upk(alo, ahi, acc2);
    float acc = alo + ahi;
    #pragma unroll
    for (int o = 16; o; o >>= 1) acc += __shfl_xor_sync(0xffffffffu, acc, o);
    if ((t & 31) == 0) red[t >> 5] = acc;
    __syncthreads();
    if (t == 0)
        out[bid] = (red[0] + red[1] + red[2] + red[3]) * (1.0f / NQ);
}

extern "C" void kernel_launch(void* const* d_in, const int* in_sizes, int n_in,
                              void* d_out, int out_size)
{
    const float *inp, *wp;
    if (in_sizes[0] == DEPTH * NQ * 3) {            // defensive input-order check
        wp  = (const float*)d_in[0];
        inp = (const float*)d_in[1];
    } else {
        inp = (const float*)d_in[0];
        wp  = (const float*)d_in[1];
    }
    int B = out_size;                                // [B,1] float output
    qsim_kernel<<<B, TPB>>>(inp, wp, (float*)d_out);
}

// round 5
// speedup vs baseline: 1.2001x; 1.2001x over previous
#include <cuda_runtime.h>

#define NQ    12
#define DEPTH 6
#define TPB   128

typedef unsigned int u32;

// ---------------------------------------------------------------------------
// Wire q <-> flat-index bit (11-q). CNOT ring tracked as GF(2)-linear storage
// permutation; Q_d = F^d columns precomputed (with smem swizzle composed in).
// ---------------------------------------------------------------------------
__host__ __device__ constexpr u32 Fmap(u32 b) {
    for (int g = 11; g >= 0; --g) {
        int c = 11 - g, t = (c + 11) % NQ;
        b ^= ((b >> c) & 1u) << t;
    }
    return b;
}
__host__ __device__ constexpr u32 Finvmap(u32 b) {
    for (int g = 0; g < NQ; ++g) {
        int c = 11 - g, t = (c + 11) % NQ;
        b ^= ((b >> c) & 1u) << t;
    }
    return b;
}
__host__ __device__ constexpr u32 swz(u32 x) { return x ^ ((x >> 5) & 31u); }

struct Tabs {
    u32 q[DEPTH][NQ];  // swizzled columns of Q_d = F^d
    u32 finv[NQ];      // columns of F^{-1} (logical space, for final weights)
};
__host__ __device__ constexpr Tabs mk_tabs() {
    Tabs t{};
    u32 raw[NQ] = {};
    for (int j = 0; j < NQ; ++j) { raw[j] = 1u << j; t.q[0][j] = swz(raw[j]); }
    for (int d = 1; d < DEPTH; ++d)
        for (int j = 0; j < NQ; ++j) { raw[j] = Fmap(raw[j]); t.q[d][j] = swz(raw[j]); }
    for (int j = 0; j < NQ; ++j) t.finv[j] = Finvmap(1u << j);
    return t;
}
__constant__ Tabs TAB = mk_tabs();

// Pass p owns 5 bit-directions (gates on first 4); filler bits from tid.
__constant__ int DIRS[3][5] = {{0,1,2,3,4},{4,5,6,7,8},{8,9,10,11,0}};
__constant__ int FILL[3][7] = {{5,6,7,8,9,10,11},{0,1,2,3,9,10,11},{1,2,3,4,5,6,7}};

__device__ __forceinline__ float2 cmul(float2 a, float2 b) {
    return make_float2(fmaf(a.x, b.x, -a.y * b.y), fmaf(a.x, b.y, a.y * b.x));
}

__global__ void __launch_bounds__(TPB, 4)
qsim_kernel(const float* __restrict__ inp, const float* __restrict__ wp,
            float* __restrict__ out)
{
    __shared__ float2 sv[1 << NQ];               // 32 KB state (AoS re,im)
    __shared__ float2 gms[DEPTH * NQ * 2];       // m00,m01 per gate (SU(2))
    __shared__ float2 vtab[NQ][2];               // per-qubit prep 2-vectors
    __shared__ float  red[TPB / 32];

    const int t   = threadIdx.x;
    const int bid = blockIdx.x;

    // ---- per-block prep ----------------------------------------------------
    if (t < NQ) {
        // fold encode RY(x) with layer-1 Rot into one complex 2-vector/qubit
        float x = inp[bid * NQ + (11 - t)];      // bit t <- wire 11-t
        float sx, cx; sincosf(0.5f * x, &sx, &cx);
        int wo = (11 - t) * 3;                   // w[0][wire]
        float phi = wp[wo + 0], th = wp[wo + 1], om = wp[wo + 2];
        float st, ct; sincosf(0.5f * th, &st, &ct);
        float sa, ca; sincosf(0.5f * (phi + om), &sa, &ca);
        float sb, cb; sincosf(0.5f * (phi - om), &sb, &cb);
        float2 m00 = make_float2( ct * ca, -ct * sa);
        float2 m01 = make_float2(-st * cb, -st * sb);
        float2 m10 = make_float2( st * cb, -st * sb);   // = -conj(m01)
        float2 m11 = make_float2( ct * ca,  ct * sa);   // =  conj(m00)
        vtab[t][0] = make_float2(fmaf(m00.x, cx, m01.x * sx), fmaf(m00.y, cx, m01.y * sx));
        vtab[t][1] = make_float2(fmaf(m10.x, cx, m11.x * sx), fmaf(m10.y, cx, m11.y * sx));
    } else if (t < DEPTH * NQ) {
        // gate matrices for layers 2..6 (d = 1..5); SU(2): keep m00,m01 only
        int d = t / NQ, m = t % NQ;              // m = bit index, wire = 11-m
        int wo = (d * NQ + (11 - m)) * 3;
        float phi = wp[wo + 0], th = wp[wo + 1], om = wp[wo + 2];
        float st, ct; sincosf(0.5f * th, &st, &ct);
        float sa, ca; sincosf(0.5f * (phi + om), &sa, &ca);
        float sb, cb; sincosf(0.5f * (phi - om), &sb, &cb);
        gms[t * 2 + 0] = make_float2( ct * ca, -ct * sa);   // m00
        gms[t * 2 + 1] = make_float2(-st * cb, -st * sb);   // m01
    }
    __syncthreads();

    // ---- prep pass: build psi_1 (encode + layer-1 Rot) and store ----------
    {
        const u32* qc = TAB.q[0];
        u32 pb = 0;
        #pragma unroll
        for (int j = 0; j < 7; ++j)
            if ((t >> j) & 1) pb ^= qc[FILL[0][j]];     // logical bits 5..11
        u32 qd[5];
        #pragma unroll
        for (int k = 0; k < 5; ++k) qd[k] = qc[DIRS[0][k]];

        float2 f = vtab[5][t & 1];
        #pragma unroll
        for (int j = 1; j < 7; ++j) f = cmul(f, vtab[5 + j][(t >> j) & 1]);
        float2 v[32]; v[0] = f;
        #pragma unroll
        for (int j = 0; j < 5; ++j) {
            #pragma unroll
            for (int k = 0; k < (1 << j); ++k) {
                float2 lo = v[k];
                v[k]            = cmul(lo, vtab[j][0]);
                v[k + (1 << j)] = cmul(lo, vtab[j][1]);
            }
        }
        #pragma unroll
        for (int c = 0; c < 32; ++c) {
            u32 a = pb;
            if (c & 1)  a ^= qd[0];
            if (c & 2)  a ^= qd[1];
            if (c & 4)  a ^= qd[2];
            if (c & 8)  a ^= qd[3];
            if (c & 16) a ^= qd[4];
            sv[a] = v[c];
        }
        __syncthreads();
    }

    float acc = 0.f;

    // ---- variational layers 2..6 -------------------------------------------
    for (int d = 1; d < DEPTH; ++d) {
        const u32* qc = TAB.q[d];
        for (int p = 0; p < 3; ++p) {
            u32 pb = 0;
            #pragma unroll
            for (int j = 0; j < 7; ++j)
                if ((t >> j) & 1) pb ^= qc[FILL[p][j]];
            u32 qd[5];
            #pragma unroll
            for (int k = 0; k < 5; ++k) qd[k] = qc[DIRS[p][k]];

            float2 s[32];
            #pragma unroll
            for (int c = 0; c < 32; ++c) {
                u32 a = pb;
                if (c & 1)  a ^= qd[0];
                if (c & 2)  a ^= qd[1];
                if (c & 4)  a ^= qd[2];
                if (c & 8)  a ^= qd[3];
                if (c & 16) a ^= qd[4];
                s[c] = sv[a];
            }

            // ---- 4 register-resident SU(2) gates on owned bits p*4..p*4+3 --
            const float2* g2 = &gms[(d * NQ + p * 4) * 2];
            #pragma unroll
            for (int g = 0; g < 4; ++g) {
                float2 u = g2[2 * g + 0], v = g2[2 * g + 1];   // m00, m01
                #pragma unroll
                for (int c = 0; c < 32; ++c) {
                    if (!((c >> g) & 1)) {
                        float2 a0 = s[c], a1 = s[c | (1 << g)];
                        float2 n0, n1;
                        n0.x = fmaf(u.x, a0.x, fmaf(-u.y, a0.y, fmaf(v.x, a1.x, -v.y * a1.y)));
                        n0.y = fmaf(u.x, a0.y, fmaf( u.y, a0.x, fmaf(v.x, a1.y,  v.y * a1.x)));
                        n1.x = fmaf(u.x, a1.x, fmaf( u.y, a1.y, fmaf(-v.x, a0.x, -v.y * a0.y)));
                        n1.y = fmaf(u.x, a1.y, fmaf(-u.y, a1.x, fmaf( v.y, a0.x, -v.x * a0.y)));
                        s[c] = n0; s[c | (1 << g)] = n1;
                    }
                }
            }

            if (d == DEPTH - 1 && p == 2) {
                // ---- fold final ring + <Z> mean into the reduction ---------
                u32 fb = 0;
                #pragma unroll
                for (int j = 0; j < 7; ++j)
                    if ((t >> j) & 1) fb ^= TAB.finv[FILL[2][j]];
                u32 fd[5];
                #pragma unroll
                for (int k = 0; k < 5; ++k) fd[k] = TAB.finv[DIRS[2][k]];
                #pragma unroll
                for (int c = 0; c < 32; ++c) {
                    u32 fv = fb;
                    if (c & 1)  fv ^= fd[0];
                    if (c & 2)  fv ^= fd[1];
                    if (c & 4)  fv ^= fd[2];
                    if (c & 8)  fv ^= fd[3];
                    if (c & 16) fv ^= fd[4];
                    float wgt = (float)(NQ - 2 * __popc(fv));
                    acc = fmaf(fmaf(s[c].x, s[c].x, s[c].y * s[c].y), wgt, acc);
                }
            } else {
                #pragma unroll
                for (int c = 0; c < 32; ++c) {
                    u32 a = pb;
                    if (c & 1)  a ^= qd[0];
                    if (c & 2)  a ^= qd[1];
                    if (c & 4)  a ^= qd[2];
                    if (c & 8)  a ^= qd[3];
                    if (c & 16) a ^= qd[4];
                    sv[a] = s[c];
                }
                __syncthreads();
            }
        }
    }

    // ---- block reduction -> out[bid] ----
    #pragma unroll
    for (int o = 16; o; o >>= 1) acc += __shfl_xor_sync(0xffffffffu, acc, o);
    if ((t & 31) == 0) red[t >> 5] = acc;
    __syncthreads();
    if (t == 0)
        out[bid] = (red[0] + red[1] + red[2] + red[3]) * (1.0f / NQ);
}

extern "C" void kernel_launch(void* const* d_in, const int* in_sizes, int n_in,
                              void* d_out, int out_size)
{
    const float *inp, *wp;
    if (in_sizes[0] == DEPTH * NQ * 3) {            // defensive input-order check
        wp  = (const float*)d_in[0];
        inp = (const float*)d_in[1];
    } else {
        inp = (const float*)d_in[0];
        wp  = (const float*)d_in[1];
    }
    int B = out_size;                                // [B,1] float output
    qsim_kernel<<<B, TPB>>>(inp, wp, (float*)d_out);
}